// round 1
// baseline (speedup 1.0000x reference)
#include <cuda_runtime.h>
#include <math.h>

// Problem constants
// B=4, S=4096, E=1024, KD=VD=1024
#define BM 128
#define BN 128
#define BK 8

// Static scratch (no allocation allowed in kernel_launch)
__device__ float g_Q[4 * 4096 * 1024];          // 64 MB
__device__ float g_K[4 * 4096 * 1024];          // 64 MB
__device__ float g_V[4 * 4096 * 1024];          // 64 MB
__device__ float g_P[67108864];                 // 4*4096*4096 = 256 MB

// Classic 128x128x8 fp32 SGEMM, 256 threads, 8x8 per-thread microtile.
// A: row-major [M,K], lda
// TRANSB=false: B row-major [K,N], ldb ; TRANSB=true: B row-major [N,K], ldb (C = A * B^T)
// C: row-major [M,N], ldc.  C = alpha * A*B (+ bias[n] if BIAS)
// blockIdx.z batches with the given strides.
template <bool TRANSB, bool BIAS>
__global__ void __launch_bounds__(256) sgemm_k(
    const float* __restrict__ A, const float* __restrict__ B,
    const float* __restrict__ bias, float* __restrict__ C,
    int M, int N, int K, int lda, int ldb, int ldc, float alpha,
    long strideA, long strideB, long strideC)
{
    const long bz = blockIdx.z;
    A += bz * strideA;
    B += bz * strideB;
    C += bz * strideC;

    __shared__ float As[BK][BM];
    __shared__ float Bs[BK][BN];

    const int tid = threadIdx.x;
    const int tx = tid & 15;        // 0..15
    const int ty = tid >> 4;        // 0..15
    const int m0 = blockIdx.y * BM;
    const int n0 = blockIdx.x * BN;

    // A-tile (and B-tile when TRANSB) load mapping: 128 rows x 8 k, float4 along k
    const int arow  = tid >> 1;            // 0..127
    const int akcol = (tid & 1) * 4;       // 0 or 4
    // B-tile (NN) load mapping: 8 k-rows x 128 n, float4 along n
    const int bkrow = tid >> 5;            // 0..7
    const int bcol  = (tid & 31) * 4;      // 0..124

    const float* Aptr = A + (long)(m0 + arow) * lda + akcol;
    const float* Bptr;
    if (TRANSB) {
        Bptr = B + (long)(n0 + arow) * ldb + akcol;
    } else {
        Bptr = B + (long)bkrow * ldb + n0 + bcol;
    }

    float acc[8][8];
#pragma unroll
    for (int i = 0; i < 8; i++)
#pragma unroll
        for (int j = 0; j < 8; j++) acc[i][j] = 0.f;

    for (int k0 = 0; k0 < K; k0 += BK) {
        // load A tile (transpose into As[k][m])
        float4 av = *(const float4*)(Aptr + k0);
        As[akcol + 0][arow] = av.x;
        As[akcol + 1][arow] = av.y;
        As[akcol + 2][arow] = av.z;
        As[akcol + 3][arow] = av.w;
        // load B tile
        if (TRANSB) {
            float4 bv = *(const float4*)(Bptr + k0);
            Bs[akcol + 0][arow] = bv.x;
            Bs[akcol + 1][arow] = bv.y;
            Bs[akcol + 2][arow] = bv.z;
            Bs[akcol + 3][arow] = bv.w;
        } else {
            float4 bv = *(const float4*)(Bptr + (long)k0 * ldb);
            *(float4*)&Bs[bkrow][bcol] = bv;
        }
        __syncthreads();

#pragma unroll
        for (int kk = 0; kk < BK; kk++) {
            float4 a0 = *(const float4*)&As[kk][ty * 4];
            float4 a1 = *(const float4*)&As[kk][64 + ty * 4];
            float4 b0 = *(const float4*)&Bs[kk][tx * 4];
            float4 b1 = *(const float4*)&Bs[kk][64 + tx * 4];
            float ar[8] = {a0.x, a0.y, a0.z, a0.w, a1.x, a1.y, a1.z, a1.w};
            float br[8] = {b0.x, b0.y, b0.z, b0.w, b1.x, b1.y, b1.z, b1.w};
#pragma unroll
            for (int i = 0; i < 8; i++)
#pragma unroll
                for (int j = 0; j < 8; j++) acc[i][j] += ar[i] * br[j];
        }
        __syncthreads();
    }

    // epilogue
#pragma unroll
    for (int i = 0; i < 8; i++) {
        int m = m0 + ((i < 4) ? (ty * 4 + i) : (64 + ty * 4 + (i - 4)));
#pragma unroll
        for (int jb = 0; jb < 2; jb++) {
            int n = n0 + jb * 64 + tx * 4;
            float4 v;
            v.x = alpha * acc[i][jb * 4 + 0];
            v.y = alpha * acc[i][jb * 4 + 1];
            v.z = alpha * acc[i][jb * 4 + 2];
            v.w = alpha * acc[i][jb * 4 + 3];
            if (BIAS) {
                v.x += bias[n + 0];
                v.y += bias[n + 1];
                v.z += bias[n + 2];
                v.w += bias[n + 3];
            }
            *(float4*)&C[(long)m * ldc + n] = v;
        }
    }
}

// One CTA (256 threads) per row; in-place softmax over `cols` elements.
__global__ void __launch_bounds__(256) softmax_rows(float* __restrict__ P, int cols)
{
    float* p = P + (long)blockIdx.x * (long)cols;
    const int tid = threadIdx.x;
    __shared__ float red[8];

    float vmax = -1e30f;
    for (int i = tid; i < cols; i += 256) vmax = fmaxf(vmax, p[i]);
#pragma unroll
    for (int o = 16; o; o >>= 1) vmax = fmaxf(vmax, __shfl_xor_sync(0xffffffffu, vmax, o));
    if ((tid & 31) == 0) red[tid >> 5] = vmax;
    __syncthreads();
    vmax = red[0];
#pragma unroll
    for (int w = 1; w < 8; w++) vmax = fmaxf(vmax, red[w]);

    float s = 0.f;
    for (int i = tid; i < cols; i += 256) {
        float e = __expf(p[i] - vmax);
        p[i] = e;
        s += e;
    }
#pragma unroll
    for (int o = 16; o; o >>= 1) s += __shfl_xor_sync(0xffffffffu, s, o);
    __syncthreads();
    if ((tid & 31) == 0) red[tid >> 5] = s;
    __syncthreads();
    s = 0.f;
#pragma unroll
    for (int w = 0; w < 8; w++) s += red[w];

    float inv = 1.f / s;
    for (int i = tid; i < cols; i += 256) p[i] *= inv;
}

extern "C" void kernel_launch(void* const* d_in, const int* in_sizes, int n_in,
                              void* d_out, int out_size)
{
    const float* x  = (const float*)d_in[0];
    const float* Wq = (const float*)d_in[1];
    const float* bq = (const float*)d_in[2];
    const float* Wk = (const float*)d_in[3];
    const float* bk = (const float*)d_in[4];
    const float* Wv = (const float*)d_in[5];
    const float* bv = (const float*)d_in[6];
    float* out = (float*)d_out;

    float *Q, *K, *V, *P;
    cudaGetSymbolAddress((void**)&Q, g_Q);
    cudaGetSymbolAddress((void**)&K, g_K);
    cudaGetSymbolAddress((void**)&V, g_V);
    cudaGetSymbolAddress((void**)&P, g_P);

    const dim3 blk(256);
    const float scale = 0.03125f;  // 1/sqrt(1024)

    // Projections: [16384,1024] = X[16384,1024] * W[1024,1024] + b
    sgemm_k<false, true><<<dim3(8, 128, 1), blk>>>(
        x, Wq, bq, Q, 16384, 1024, 1024, 1024, 1024, 1024, 1.0f, 0, 0, 0);
    sgemm_k<false, true><<<dim3(8, 128, 1), blk>>>(
        x, Wk, bk, K, 16384, 1024, 1024, 1024, 1024, 1024, 1.0f, 0, 0, 0);
    sgemm_k<false, true><<<dim3(8, 128, 1), blk>>>(
        x, Wv, bv, V, 16384, 1024, 1024, 1024, 1024, 1024, 1.0f, 0, 0, 0);

    // Scores: per batch, P[4096,4096] = scale * Q * K^T
    sgemm_k<true, false><<<dim3(32, 32, 4), blk>>>(
        Q, K, nullptr, P, 4096, 4096, 1024, 1024, 1024, 4096, scale,
        4194304L, 4194304L, 16777216L);

    // Softmax over each of the 4*4096 rows (4096 cols)
    softmax_rows<<<16384, 256>>>(P, 4096);

    // Out: per batch, O[4096,1024] = P[4096,4096] * V[4096,1024]
    sgemm_k<false, false><<<dim3(8, 32, 4), blk>>>(
        P, V, nullptr, out, 4096, 1024, 4096, 4096, 1024, 1024, 1.0f,
        16777216L, 4194304L, 4194304L);
}

// round 3
// speedup vs baseline: 2.7933x; 2.7933x over previous
#include <cuda_runtime.h>
#include <cuda_bf16.h>
#include <stdint.h>

// ---------------- constants ----------------
#define TM 128
#define TN 128
#define KC 32          // k-slab (bf16 elements)
#define RS 40          // smem row stride in bf16 elems (80 B, conflict-free for ldmatrix)
#define TILE_B (128 * RS * 2)     // 10240 B per tile
#define T_AH 0
#define T_AL (1 * TILE_B)
#define T_BH (2 * TILE_B)
#define T_BL (3 * TILE_B)
#define STAGE_B (4 * TILE_B)      // 40960
#define SMEM_DYN (2 * STAGE_B)    // 81920

// ---------------- static scratch (no allocs allowed) ----------------
__device__ __nv_bfloat16 g_Xhi[16384L*1024], g_Xlo[16384L*1024];
__device__ __nv_bfloat16 g_Wthi[3L*1024*1024], g_Wtlo[3L*1024*1024];
__device__ __nv_bfloat16 g_Qhi[16384L*1024], g_Qlo[16384L*1024];
__device__ __nv_bfloat16 g_Khi[16384L*1024], g_Klo[16384L*1024];
__device__ __nv_bfloat16 g_Vhi[16384L*1024], g_Vlo[16384L*1024];
__device__ __nv_bfloat16 g_Vthi[16384L*1024], g_Vtlo[16384L*1024];
__device__ float         g_P  [67108864L];
__device__ __nv_bfloat16 g_Phi[67108864L], g_Plo[67108864L];

// ---------------- helpers ----------------
__device__ __forceinline__ uint32_t smem_u32(const void* p) {
    uint32_t r;
    asm("{ .reg .u64 t; cvta.to.shared.u64 t, %1; cvt.u32.u64 %0, t; }" : "=r"(r) : "l"(p));
    return r;
}

__device__ __forceinline__ void split2(float a, float b, uint32_t& h, uint32_t& l) {
    __nv_bfloat16 ha = __float2bfloat16(a), hb = __float2bfloat16(b);
    float ra = a - __bfloat162float(ha);
    float rb = b - __bfloat162float(hb);
    __nv_bfloat16 la = __float2bfloat16(ra), lb = __float2bfloat16(rb);
    h = ((uint32_t)__bfloat16_as_ushort(hb) << 16) | (uint32_t)__bfloat16_as_ushort(ha);
    l = ((uint32_t)__bfloat16_as_ushort(lb) << 16) | (uint32_t)__bfloat16_as_ushort(la);
}

__device__ __forceinline__ void ldsm4(uint32_t* r, uint32_t addr) {
    asm volatile("ldmatrix.sync.aligned.m8n8.x4.shared.b16 {%0,%1,%2,%3}, [%4];"
                 : "=r"(r[0]), "=r"(r[1]), "=r"(r[2]), "=r"(r[3]) : "r"(addr));
}

__device__ __forceinline__ void mma16816(float* c, const uint32_t* a, const uint32_t* b) {
    asm volatile(
        "mma.sync.aligned.m16n8k16.row.col.f32.bf16.bf16.f32 "
        "{%0,%1,%2,%3}, {%4,%5,%6,%7}, {%8,%9}, {%0,%1,%2,%3};"
        : "+f"(c[0]), "+f"(c[1]), "+f"(c[2]), "+f"(c[3])
        : "r"(a[0]), "r"(a[1]), "r"(a[2]), "r"(a[3]), "r"(b[0]), "r"(b[1]));
}

__device__ __forceinline__ void cpa16(uint32_t dst, const void* src) {
    asm volatile("cp.async.ca.shared.global [%0], [%1], 16;" :: "r"(dst), "l"(src));
}

// stage one 128x32-bf16 tile (k-contiguous rows) into padded smem
__device__ __forceinline__ void stage_tile(uint32_t dstb, const char* src, long ldbytes, int tid) {
#pragma unroll
    for (int t = 0; t < 2; t++) {
        int j = tid + t * 256;
        int r = j >> 2;
        int c = j & 3;
        cpa16(dstb + r * (RS * 2) + c * 16, src + (long)r * ldbytes + c * 16);
    }
}

// ---------------- bf16x3 HMMA GEMM ----------------
// C[m,n] = alpha * sum_k A[m,k]*B[n,k] (+ bias[n]); A,B bf16 hi/lo pairs, k contiguous.
// OUT_PAIR: write Chi/Clo bf16 split; else fp32 Cf.
template <bool BIAS, bool OUT_PAIR>
__global__ void __launch_bounds__(256, 2)
tgemm(const __nv_bfloat16* __restrict__ Ahi, const __nv_bfloat16* __restrict__ Alo,
      long lda, long sA,
      const __nv_bfloat16* __restrict__ Bhi, const __nv_bfloat16* __restrict__ Blo,
      long ldb, long sB,
      const float* __restrict__ bias, float alpha, int Kdim,
      float* __restrict__ Cf, __nv_bfloat16* __restrict__ Chi, __nv_bfloat16* __restrict__ Clo,
      long ldc, long sC)
{
    extern __shared__ __align__(16) char smraw[];
    const uint32_t sb = smem_u32(smraw);

    const int tid = threadIdx.x;
    const int wid = tid >> 5;
    const int lane = tid & 31;
    const long bz = blockIdx.z;
    const long m0 = (long)blockIdx.y * TM;
    const long n0 = (long)blockIdx.x * TN;

    const char* pAh = (const char*)(Ahi + bz * sA + m0 * lda);
    const char* pAl = (const char*)(Alo + bz * sA + m0 * lda);
    const char* pBh = (const char*)(Bhi + bz * sB + n0 * ldb);
    const char* pBl = (const char*)(Blo + bz * sB + n0 * ldb);
    const long ldab = lda * 2, ldbb = ldb * 2;

    // warp layout: 2 (m) x 4 (n); warp tile 64x32
    const int wm = (wid & 1) * 64;
    const int wn = (wid >> 1) * 32;

    // ldmatrix lane offsets (bytes within tile)
    const int aOffBase = (wm + (lane & 15)) * (RS * 2) + ((lane >> 4) << 4);
    const int bOffBase = (wn + ((lane >> 4) << 3) + (lane & 7)) * (RS * 2) + (((lane >> 3) & 1) << 4);

    float acc[4][4][4];
#pragma unroll
    for (int i = 0; i < 4; i++)
#pragma unroll
        for (int j = 0; j < 4; j++)
#pragma unroll
            for (int e = 0; e < 4; e++) acc[i][j][e] = 0.f;

    const int nslab = Kdim / KC;

    // prefetch slab 0 into stage 0
    stage_tile(sb + T_AH, pAh, ldab, tid);
    stage_tile(sb + T_AL, pAl, ldab, tid);
    stage_tile(sb + T_BH, pBh, ldbb, tid);
    stage_tile(sb + T_BL, pBl, ldbb, tid);
    asm volatile("cp.async.commit_group;" ::: "memory");

    for (int s = 0; s < nslab; s++) {
        if (s + 1 < nslab) {
            const uint32_t nb = sb + ((s + 1) & 1) * STAGE_B;
            const long kb = (long)(s + 1) * (KC * 2);
            stage_tile(nb + T_AH, pAh + kb, ldab, tid);
            stage_tile(nb + T_AL, pAl + kb, ldab, tid);
            stage_tile(nb + T_BH, pBh + kb, ldbb, tid);
            stage_tile(nb + T_BL, pBl + kb, ldbb, tid);
            asm volatile("cp.async.commit_group;" ::: "memory");
            asm volatile("cp.async.wait_group 1;" ::: "memory");
        } else {
            asm volatile("cp.async.wait_group 0;" ::: "memory");
        }
        __syncthreads();

        const uint32_t st = sb + (s & 1) * STAGE_B;
#pragma unroll
        for (int kk = 0; kk < 2; kk++) {
            const int ko = kk * (KC);  // kk*16 elems * 2 bytes = kk*32 bytes
            uint32_t ah[4][4], al[4][4], bh[4][2], bl[4][2];
            // A-hi frags
#pragma unroll
            for (int i = 0; i < 4; i++)
                ldsm4(ah[i], st + T_AH + aOffBase + i * 16 * (RS * 2) + ko);
            // B-hi frags (x4 covers two n8 frags x two k8 halves)
#pragma unroll
            for (int jp = 0; jp < 2; jp++) {
                uint32_t r[4];
                ldsm4(r, st + T_BH + bOffBase + jp * 16 * (RS * 2) + ko);
                bh[2 * jp][0] = r[0]; bh[2 * jp][1] = r[1];
                bh[2 * jp + 1][0] = r[2]; bh[2 * jp + 1][1] = r[3];
            }
            // hi * hi
#pragma unroll
            for (int i = 0; i < 4; i++)
#pragma unroll
                for (int j = 0; j < 4; j++) mma16816(acc[i][j], ah[i], bh[j]);
            // B-lo frags, hi * lo
#pragma unroll
            for (int jp = 0; jp < 2; jp++) {
                uint32_t r[4];
                ldsm4(r, st + T_BL + bOffBase + jp * 16 * (RS * 2) + ko);
                bl[2 * jp][0] = r[0]; bl[2 * jp][1] = r[1];
                bl[2 * jp + 1][0] = r[2]; bl[2 * jp + 1][1] = r[3];
            }
#pragma unroll
            for (int i = 0; i < 4; i++)
#pragma unroll
                for (int j = 0; j < 4; j++) mma16816(acc[i][j], ah[i], bl[j]);
            // A-lo frags, lo * hi
#pragma unroll
            for (int i = 0; i < 4; i++)
                ldsm4(al[i], st + T_AL + aOffBase + i * 16 * (RS * 2) + ko);
#pragma unroll
            for (int i = 0; i < 4; i++)
#pragma unroll
                for (int j = 0; j < 4; j++) mma16816(acc[i][j], al[i], bh[j]);
        }
        __syncthreads();
    }

    // epilogue
#pragma unroll
    for (int i = 0; i < 4; i++) {
        const long r0 = m0 + wm + i * 16 + (lane >> 2);
        const long r1 = r0 + 8;
#pragma unroll
        for (int j = 0; j < 4; j++) {
            const int cb = (int)n0 + wn + j * 8 + (lane & 3) * 2;
            float v0 = alpha * acc[i][j][0];
            float v1 = alpha * acc[i][j][1];
            float v2 = alpha * acc[i][j][2];
            float v3 = alpha * acc[i][j][3];
            if (BIAS) {
                const float b0 = bias[cb], b1 = bias[cb + 1];
                v0 += b0; v1 += b1; v2 += b0; v3 += b1;
            }
            if (OUT_PAIR) {
                uint32_t h, l;
                split2(v0, v1, h, l);
                *(uint32_t*)(Chi + bz * sC + r0 * ldc + cb) = h;
                *(uint32_t*)(Clo + bz * sC + r0 * ldc + cb) = l;
                split2(v2, v3, h, l);
                *(uint32_t*)(Chi + bz * sC + r1 * ldc + cb) = h;
                *(uint32_t*)(Clo + bz * sC + r1 * ldc + cb) = l;
            } else {
                *(float2*)(Cf + bz * sC + r0 * ldc + cb) = make_float2(v0, v1);
                *(float2*)(Cf + bz * sC + r1 * ldc + cb) = make_float2(v2, v3);
            }
        }
    }
}

// ---------------- pre/post passes ----------------
__global__ void __launch_bounds__(256) convert_x(const float4* __restrict__ x,
                                                 uint2* __restrict__ hi, uint2* __restrict__ lo)
{
    long i = (long)blockIdx.x * 256 + threadIdx.x;
    float4 v = x[i];
    uint32_t h0, l0, h1, l1;
    split2(v.x, v.y, h0, l0);
    split2(v.z, v.w, h1, l1);
    hi[i] = make_uint2(h0, h1);
    lo[i] = make_uint2(l0, l1);
}

__global__ void __launch_bounds__(256) convert_wt(const float* __restrict__ W0,
                                                  const float* __restrict__ W1,
                                                  const float* __restrict__ W2,
                                                  __nv_bfloat16* __restrict__ hi,
                                                  __nv_bfloat16* __restrict__ lo)
{
    const float* W = (blockIdx.z == 0) ? W0 : (blockIdx.z == 1) ? W1 : W2;
    __nv_bfloat16* ho = hi + (long)blockIdx.z * 1048576;
    __nv_bfloat16* lolo = lo + (long)blockIdx.z * 1048576;
    __shared__ float t[32][33];
    const int e0 = blockIdx.x * 32, n0 = blockIdx.y * 32;
    const int lx = threadIdx.x & 31, ly = threadIdx.x >> 5;
#pragma unroll
    for (int j = 0; j < 4; j++)
        t[ly + 8 * j][lx] = W[(long)(e0 + ly + 8 * j) * 1024 + n0 + lx];
    __syncthreads();
#pragma unroll
    for (int j = 0; j < 4; j++) {
        float v = t[lx][ly + 8 * j];
        __nv_bfloat16 h = __float2bfloat16(v);
        __nv_bfloat16 l = __float2bfloat16(v - __bfloat162float(h));
        long o = (long)(n0 + ly + 8 * j) * 1024 + e0 + lx;
        ho[o] = h;
        lolo[o] = l;
    }
}

__global__ void __launch_bounds__(256) transpose_bf(const __nv_bfloat16* __restrict__ in,
                                                    __nv_bfloat16* __restrict__ out)
{
    __shared__ ushort t[32][33];
    const int s0 = blockIdx.x * 32, n0 = blockIdx.y * 32;
    const long b = blockIdx.z;
    const ushort* ip = (const ushort*)in + b * 4194304L;
    ushort* op = (ushort*)out + b * 4194304L;
    const int lx = threadIdx.x & 31, ly = threadIdx.x >> 5;
#pragma unroll
    for (int j = 0; j < 4; j++)
        t[ly + 8 * j][lx] = ip[(long)(s0 + ly + 8 * j) * 1024 + n0 + lx];
    __syncthreads();
#pragma unroll
    for (int j = 0; j < 4; j++)
        op[(long)(n0 + ly + 8 * j) * 4096 + s0 + lx] = t[lx][ly + 8 * j];
}

__global__ void __launch_bounds__(256) softmax_k(const float* __restrict__ P,
                                                 __nv_bfloat16* __restrict__ Phi,
                                                 __nv_bfloat16* __restrict__ Plo)
{
    __shared__ float buf[4096];
    __shared__ float red[8];
    const float* p = P + (long)blockIdx.x * 4096;
    const int tid = threadIdx.x;

    float vmax = -1e30f;
    for (int i = tid; i < 4096; i += 256) {
        float v = p[i];
        buf[i] = v;
        vmax = fmaxf(vmax, v);
    }
#pragma unroll
    for (int o = 16; o; o >>= 1) vmax = fmaxf(vmax, __shfl_xor_sync(0xffffffffu, vmax, o));
    if ((tid & 31) == 0) red[tid >> 5] = vmax;
    __syncthreads();
    vmax = red[0];
#pragma unroll
    for (int w = 1; w < 8; w++) vmax = fmaxf(vmax, red[w]);
    __syncthreads();

    float s = 0.f;
    for (int i = tid; i < 4096; i += 256) {
        float e = __expf(buf[i] - vmax);
        buf[i] = e;
        s += e;
    }
#pragma unroll
    for (int o = 16; o; o >>= 1) s += __shfl_xor_sync(0xffffffffu, s, o);
    if ((tid & 31) == 0) red[tid >> 5] = s;
    __syncthreads();
    s = 0.f;
#pragma unroll
    for (int w = 0; w < 8; w++) s += red[w];

    const float inv = 1.f / s;
    __nv_bfloat16* ph = Phi + (long)blockIdx.x * 4096;
    __nv_bfloat16* pl = Plo + (long)blockIdx.x * 4096;
    for (int i = tid; i < 4096; i += 256) {
        float v = buf[i] * inv;
        __nv_bfloat16 h = __float2bfloat16(v);
        __nv_bfloat16 l = __float2bfloat16(v - __bfloat162float(h));
        ph[i] = h;
        pl[i] = l;
    }
}

// ---------------- launch ----------------
extern "C" void kernel_launch(void* const* d_in, const int* in_sizes, int n_in,
                              void* d_out, int out_size)
{
    const float* x  = (const float*)d_in[0];
    const float* Wq = (const float*)d_in[1];
    const float* bq = (const float*)d_in[2];
    const float* Wk = (const float*)d_in[3];
    const float* bk = (const float*)d_in[4];
    const float* Wv = (const float*)d_in[5];
    const float* bv = (const float*)d_in[6];
    float* out = (float*)d_out;

    __nv_bfloat16 *Xhi, *Xlo, *Wthi, *Wtlo, *Qhi, *Qlo, *Khi, *Klo, *Vhi, *Vlo,
                  *Vthi, *Vtlo, *Phi, *Plo;
    float* P;
    cudaGetSymbolAddress((void**)&Xhi, g_Xhi);
    cudaGetSymbolAddress((void**)&Xlo, g_Xlo);
    cudaGetSymbolAddress((void**)&Wthi, g_Wthi);
    cudaGetSymbolAddress((void**)&Wtlo, g_Wtlo);
    cudaGetSymbolAddress((void**)&Qhi, g_Qhi);
    cudaGetSymbolAddress((void**)&Qlo, g_Qlo);
    cudaGetSymbolAddress((void**)&Khi, g_Khi);
    cudaGetSymbolAddress((void**)&Klo, g_Klo);
    cudaGetSymbolAddress((void**)&Vhi, g_Vhi);
    cudaGetSymbolAddress((void**)&Vlo, g_Vlo);
    cudaGetSymbolAddress((void**)&Vthi, g_Vthi);
    cudaGetSymbolAddress((void**)&Vtlo, g_Vtlo);
    cudaGetSymbolAddress((void**)&P, g_P);
    cudaGetSymbolAddress((void**)&Phi, g_Phi);
    cudaGetSymbolAddress((void**)&Plo, g_Plo);

    cudaFuncSetAttribute(tgemm<true, true>, cudaFuncAttributeMaxDynamicSharedMemorySize, SMEM_DYN);
    cudaFuncSetAttribute(tgemm<false, false>, cudaFuncAttributeMaxDynamicSharedMemorySize, SMEM_DYN);

    // 1. operand conversion
    convert_x<<<16384, 256>>>((const float4*)x, (uint2*)Xhi, (uint2*)Xlo);
    convert_wt<<<dim3(32, 32, 3), 256>>>(Wq, Wk, Wv, Wthi, Wtlo);

    // 2. projections: [16384,1024] = X * W + b  -> bf16 hi/lo pairs
    tgemm<true, true><<<dim3(8, 128, 1), 256, SMEM_DYN>>>(
        Xhi, Xlo, 1024, 0, Wthi + 0L, Wtlo + 0L, 1024, 0,
        bq, 1.f, 1024, nullptr, Qhi, Qlo, 1024, 0);
    tgemm<true, true><<<dim3(8, 128, 1), 256, SMEM_DYN>>>(
        Xhi, Xlo, 1024, 0, Wthi + 1048576L, Wtlo + 1048576L, 1024, 0,
        bk, 1.f, 1024, nullptr, Khi, Klo, 1024, 0);
    tgemm<true, true><<<dim3(8, 128, 1), 256, SMEM_DYN>>>(
        Xhi, Xlo, 1024, 0, Wthi + 2097152L, Wtlo + 2097152L, 1024, 0,
        bv, 1.f, 1024, nullptr, Vhi, Vlo, 1024, 0);

    // 3. transpose V -> Vt [b, n, s]
    transpose_bf<<<dim3(128, 32, 4), 256>>>(Vhi, Vthi);
    transpose_bf<<<dim3(128, 32, 4), 256>>>(Vlo, Vtlo);

    // 4. scores: P = (1/32) * Q K^T, fp32
    tgemm<false, false><<<dim3(32, 32, 4), 256, SMEM_DYN>>>(
        Qhi, Qlo, 1024, 4194304L, Khi, Klo, 1024, 4194304L,
        nullptr, 0.03125f, 1024, P, nullptr, nullptr, 4096, 16777216L);

    // 5. softmax rows -> bf16 hi/lo
    softmax_k<<<16384, 256>>>(P, Phi, Plo);

    // 6. out = P V   (B operand = Vt, k = s contiguous)
    tgemm<false, false><<<dim3(8, 32, 4), 256, SMEM_DYN>>>(
        Phi, Plo, 4096, 16777216L, Vthi, Vtlo, 4096, 4194304L,
        nullptr, 1.f, 4096, out, nullptr, nullptr, 1024, 4194304L);
}

// round 4
// speedup vs baseline: 3.3287x; 1.1917x over previous
#include <cuda_runtime.h>
#include <cuda_fp16.h>
#include <stdint.h>

// ---------------- constants ----------------
#define TM 128
#define TN 128
#define KC 32                       // k-slab (fp16 elements)
#define RS 40                       // smem row stride in fp16 elems (80 B)
#define TILE_B (128 * RS * 2)       // 10240 B per tile
#define SM3 (2 * 4 * TILE_B)        // 3-pass: 2 stages x 4 tiles = 81920
#define SM2 (3 * 3 * TILE_B)        // 2-pass: 3 stages x 3 tiles = 92160

// ---------------- static scratch ----------------
__device__ __half g_Xhi[16384L*1024], g_Xlo[16384L*1024];
__device__ __half g_Whi[3L*1024*1024], g_Wlo[3L*1024*1024];
__device__ __half g_Qhi[16384L*1024], g_Qlo[16384L*1024];
__device__ __half g_Ks [16384L*1024];
__device__ __half g_Vs [16384L*1024];
__device__ __half g_Vt [16384L*1024];
__device__ float  g_P  [67108864L];
__device__ __half g_Phi[67108864L], g_Plo[67108864L];

// ---------------- helpers ----------------
__device__ __forceinline__ uint32_t smem_u32(const void* p) {
    uint32_t r;
    asm("{ .reg .u64 t; cvta.to.shared.u64 t, %1; cvt.u32.u64 %0, t; }" : "=r"(r) : "l"(p));
    return r;
}

__device__ __forceinline__ uint32_t packh(__half a, __half b) {
    return ((uint32_t)__half_as_ushort(b) << 16) | (uint32_t)__half_as_ushort(a);
}

// split two fp32 into packed fp16 hi-pair / lo-pair
__device__ __forceinline__ void split2h(float a, float b, uint32_t& h, uint32_t& l) {
    __half ha = __float2half_rn(a), hb = __float2half_rn(b);
    float ra = a - __half2float(ha);
    float rb = b - __half2float(hb);
    h = packh(ha, hb);
    l = packh(__float2half_rn(ra), __float2half_rn(rb));
}

__device__ __forceinline__ void ldsm4(uint32_t* r, uint32_t addr) {
    asm volatile("ldmatrix.sync.aligned.m8n8.x4.shared.b16 {%0,%1,%2,%3}, [%4];"
                 : "=r"(r[0]), "=r"(r[1]), "=r"(r[2]), "=r"(r[3]) : "r"(addr));
}

__device__ __forceinline__ void mma16816(float* c, const uint32_t* a, const uint32_t* b) {
    asm volatile(
        "mma.sync.aligned.m16n8k16.row.col.f32.f16.f16.f32 "
        "{%0,%1,%2,%3}, {%4,%5,%6,%7}, {%8,%9}, {%0,%1,%2,%3};"
        : "+f"(c[0]), "+f"(c[1]), "+f"(c[2]), "+f"(c[3])
        : "r"(a[0]), "r"(a[1]), "r"(a[2]), "r"(a[3]), "r"(b[0]), "r"(b[1]));
}

__device__ __forceinline__ void cpa16(uint32_t dst, const void* src) {
    asm volatile("cp.async.ca.shared.global [%0], [%1], 16;" :: "r"(dst), "l"(src));
}

template <int N>
__device__ __forceinline__ void cpwait() {
    asm volatile("cp.async.wait_group %0;" :: "n"(N) : "memory");
}

// stage one 128x32-fp16 tile (k-contiguous rows, 64B payload per row) into padded smem
__device__ __forceinline__ void stage_tile(uint32_t dstb, const char* src, long ldbytes, int tid) {
#pragma unroll
    for (int t = 0; t < 2; t++) {
        int j = tid + t * 256;
        int r = j >> 2;
        int c = j & 3;
        cpa16(dstb + r * (RS * 2) + c * 16, src + (long)r * ldbytes + c * 16);
    }
}

// ---------------- fp16 split HMMA GEMM ----------------
// C[m,n] = alpha * sum_k A[m,k]*B[n,k] (+ bias[n])
// PASSES==3: A pair x B pair (drop lo*lo). PASSES==2: A pair x B single.
// OUTM: 0 = fp32 Cf ; 1 = fp16 pair (C1 hi, C2 lo) ; 2 = fp16 single (C1)
template <int PASSES, int NS, bool BIAS, int OUTM>
__global__ void __launch_bounds__(256, 2)
tgemm(const __half* __restrict__ Ahi, const __half* __restrict__ Alo, long lda, long sA,
      const __half* __restrict__ Bhi, const __half* __restrict__ Blo, long ldb, long sB,
      const float* __restrict__ bias, float alpha, int Kdim,
      float* __restrict__ Cf, __half* __restrict__ C1, __half* __restrict__ C2,
      long ldc, long sC)
{
    constexpr int NT = (PASSES == 3) ? 4 : 3;
    constexpr int STAGE = NT * TILE_B;
    constexpr int T_AH = 0, T_AL = TILE_B, T_B0 = 2 * TILE_B, T_B1 = 3 * TILE_B;

    extern __shared__ __align__(16) char smraw[];
    const uint32_t sb = smem_u32(smraw);

    const int tid = threadIdx.x;
    const int wid = tid >> 5;
    const int lane = tid & 31;
    const long bz = blockIdx.z;
    const long m0 = (long)blockIdx.y * TM;
    const long n0 = (long)blockIdx.x * TN;

    const char* pAh = (const char*)(Ahi + bz * sA + m0 * lda);
    const char* pAl = (const char*)(Alo + bz * sA + m0 * lda);
    const char* pBh = (const char*)(Bhi + bz * sB + n0 * ldb);
    const char* pBl = (PASSES == 3) ? (const char*)(Blo + bz * sB + n0 * ldb) : nullptr;
    const long ldab = lda * 2, ldbb = ldb * 2;

    // warp layout: 2 (m) x 4 (n); warp tile 64x32
    const int wm = (wid & 1) * 64;
    const int wn = (wid >> 1) * 32;
    const int aOffBase = (wm + (lane & 15)) * (RS * 2) + ((lane >> 4) << 4);
    const int bOffBase = (wn + ((lane >> 4) << 3) + (lane & 7)) * (RS * 2) + (((lane >> 3) & 1) << 4);

    float acc[4][4][4];
#pragma unroll
    for (int i = 0; i < 4; i++)
#pragma unroll
        for (int j = 0; j < 4; j++)
#pragma unroll
            for (int e = 0; e < 4; e++) acc[i][j][e] = 0.f;

    const int nslab = Kdim / KC;

    // stage one slab
    auto stage = [&](int idx) {
        const uint32_t base = sb + (uint32_t)(idx % NS) * STAGE;
        const long kb = (long)idx * (KC * 2);
        stage_tile(base + T_AH, pAh + kb, ldab, tid);
        stage_tile(base + T_AL, pAl + kb, ldab, tid);
        stage_tile(base + T_B0, pBh + kb, ldbb, tid);
        if (PASSES == 3) stage_tile(base + T_B1, pBl + kb, ldbb, tid);
        asm volatile("cp.async.commit_group;" ::: "memory");
    };

    // prologue: stages 0..NS-2
#pragma unroll
    for (int p = 0; p < NS - 1; p++) stage(p);

    for (int s = 0; s < nslab; s++) {
        if (s + NS - 1 < nslab) {
            stage(s + NS - 1);
            cpwait<NS - 1>();
        } else {
            cpwait<0>();
        }
        __syncthreads();

        const uint32_t st = sb + (uint32_t)(s % NS) * STAGE;
#pragma unroll
        for (int kk = 0; kk < 2; kk++) {
            const int ko = kk * 32;  // 16 elems * 2 B
            uint32_t ah[4][4], al[4][4], bh[4][2];
#pragma unroll
            for (int i = 0; i < 4; i++)
                ldsm4(ah[i], st + T_AH + aOffBase + i * 16 * (RS * 2) + ko);
#pragma unroll
            for (int jp = 0; jp < 2; jp++) {
                uint32_t r[4];
                ldsm4(r, st + T_B0 + bOffBase + jp * 16 * (RS * 2) + ko);
                bh[2 * jp][0] = r[0]; bh[2 * jp][1] = r[1];
                bh[2 * jp + 1][0] = r[2]; bh[2 * jp + 1][1] = r[3];
            }
#pragma unroll
            for (int i = 0; i < 4; i++)
#pragma unroll
                for (int j = 0; j < 4; j++) mma16816(acc[i][j], ah[i], bh[j]);

            if (PASSES == 3) {
                uint32_t bl[4][2];
#pragma unroll
                for (int jp = 0; jp < 2; jp++) {
                    uint32_t r[4];
                    ldsm4(r, st + T_B1 + bOffBase + jp * 16 * (RS * 2) + ko);
                    bl[2 * jp][0] = r[0]; bl[2 * jp][1] = r[1];
                    bl[2 * jp + 1][0] = r[2]; bl[2 * jp + 1][1] = r[3];
                }
#pragma unroll
                for (int i = 0; i < 4; i++)
#pragma unroll
                    for (int j = 0; j < 4; j++) mma16816(acc[i][j], ah[i], bl[j]);
            }
#pragma unroll
            for (int i = 0; i < 4; i++)
                ldsm4(al[i], st + T_AL + aOffBase + i * 16 * (RS * 2) + ko);
#pragma unroll
            for (int i = 0; i < 4; i++)
#pragma unroll
                for (int j = 0; j < 4; j++) mma16816(acc[i][j], al[i], bh[j]);
        }
        __syncthreads();
    }

    // epilogue
#pragma unroll
    for (int i = 0; i < 4; i++) {
        const long r0 = m0 + wm + i * 16 + (lane >> 2);
        const long r1 = r0 + 8;
#pragma unroll
        for (int j = 0; j < 4; j++) {
            const int cb = (int)n0 + wn + j * 8 + (lane & 3) * 2;
            float v0 = alpha * acc[i][j][0];
            float v1 = alpha * acc[i][j][1];
            float v2 = alpha * acc[i][j][2];
            float v3 = alpha * acc[i][j][3];
            if (BIAS) {
                const float b0 = bias[cb], b1 = bias[cb + 1];
                v0 += b0; v1 += b1; v2 += b0; v3 += b1;
            }
            if (OUTM == 0) {
                *(float2*)(Cf + bz * sC + r0 * ldc + cb) = make_float2(v0, v1);
                *(float2*)(Cf + bz * sC + r1 * ldc + cb) = make_float2(v2, v3);
            } else if (OUTM == 1) {
                uint32_t h, l;
                split2h(v0, v1, h, l);
                *(uint32_t*)(C1 + bz * sC + r0 * ldc + cb) = h;
                *(uint32_t*)(C2 + bz * sC + r0 * ldc + cb) = l;
                split2h(v2, v3, h, l);
                *(uint32_t*)(C1 + bz * sC + r1 * ldc + cb) = h;
                *(uint32_t*)(C2 + bz * sC + r1 * ldc + cb) = l;
            } else {
                *(uint32_t*)(C1 + bz * sC + r0 * ldc + cb) =
                    packh(__float2half_rn(v0), __float2half_rn(v1));
                *(uint32_t*)(C1 + bz * sC + r1 * ldc + cb) =
                    packh(__float2half_rn(v2), __float2half_rn(v3));
            }
        }
    }
}

// ---------------- pre/post passes ----------------
__global__ void __launch_bounds__(256) convert_x(const float4* __restrict__ x,
                                                 uint2* __restrict__ hi, uint2* __restrict__ lo)
{
    long i = (long)blockIdx.x * 256 + threadIdx.x;
    float4 v = x[i];
    uint32_t h0, l0, h1, l1;
    split2h(v.x, v.y, h0, l0);
    split2h(v.z, v.w, h1, l1);
    hi[i] = make_uint2(h0, h1);
    lo[i] = make_uint2(l0, l1);
}

__global__ void __launch_bounds__(256) convert_wt(const float* __restrict__ W0,
                                                  const float* __restrict__ W1,
                                                  const float* __restrict__ W2,
                                                  __half* __restrict__ hi,
                                                  __half* __restrict__ lo)
{
    const float* W = (blockIdx.z == 0) ? W0 : (blockIdx.z == 1) ? W1 : W2;
    __half* ho = hi + (long)blockIdx.z * 1048576;
    __half* lw = lo + (long)blockIdx.z * 1048576;
    __shared__ float t[32][33];
    const int e0 = blockIdx.x * 32, n0 = blockIdx.y * 32;
    const int lx = threadIdx.x & 31, ly = threadIdx.x >> 5;
#pragma unroll
    for (int j = 0; j < 4; j++)
        t[ly + 8 * j][lx] = W[(long)(e0 + ly + 8 * j) * 1024 + n0 + lx];
    __syncthreads();
#pragma unroll
    for (int j = 0; j < 4; j++) {
        float v = t[lx][ly + 8 * j];
        __half h = __float2half_rn(v);
        __half l = __float2half_rn(v - __half2float(h));
        long o = (long)(n0 + ly + 8 * j) * 1024 + e0 + lx;
        ho[o] = h;
        lw[o] = l;
    }
}

__global__ void __launch_bounds__(256) transpose_h(const __half* __restrict__ in,
                                                   __half* __restrict__ out)
{
    __shared__ ushort t[32][33];
    const int s0 = blockIdx.x * 32, n0 = blockIdx.y * 32;
    const long b = blockIdx.z;
    const ushort* ip = (const ushort*)in + b * 4194304L;
    ushort* op = (ushort*)out + b * 4194304L;
    const int lx = threadIdx.x & 31, ly = threadIdx.x >> 5;
#pragma unroll
    for (int j = 0; j < 4; j++)
        t[ly + 8 * j][lx] = ip[(long)(s0 + ly + 8 * j) * 1024 + n0 + lx];
    __syncthreads();
#pragma unroll
    for (int j = 0; j < 4; j++)
        op[(long)(n0 + ly + 8 * j) * 4096 + s0 + lx] = t[lx][ly + 8 * j];
}

__global__ void __launch_bounds__(256) softmax_k(const float* __restrict__ P,
                                                 __half* __restrict__ Phi,
                                                 __half* __restrict__ Plo)
{
    __shared__ float buf[4096];
    __shared__ float red[8];
    const float* p = P + (long)blockIdx.x * 4096;
    const int tid = threadIdx.x;

    float vmax = -1e30f;
    for (int i = tid; i < 4096; i += 256) {
        float v = p[i];
        buf[i] = v;
        vmax = fmaxf(vmax, v);
    }
#pragma unroll
    for (int o = 16; o; o >>= 1) vmax = fmaxf(vmax, __shfl_xor_sync(0xffffffffu, vmax, o));
    if ((tid & 31) == 0) red[tid >> 5] = vmax;
    __syncthreads();
    vmax = red[0];
#pragma unroll
    for (int w = 1; w < 8; w++) vmax = fmaxf(vmax, red[w]);
    __syncthreads();

    float s = 0.f;
    for (int i = tid; i < 4096; i += 256) {
        float e = __expf(buf[i] - vmax);
        buf[i] = e;
        s += e;
    }
#pragma unroll
    for (int o = 16; o; o >>= 1) s += __shfl_xor_sync(0xffffffffu, s, o);
    if ((tid & 31) == 0) red[tid >> 5] = s;
    __syncthreads();
    s = 0.f;
#pragma unroll
    for (int w = 0; w < 8; w++) s += red[w];

    const float inv = 1.f / s;
    __half* ph = Phi + (long)blockIdx.x * 4096;
    __half* pl = Plo + (long)blockIdx.x * 4096;
    for (int i = tid; i < 4096; i += 256) {
        float v = buf[i] * inv;
        __half h = __float2half_rn(v);
        ph[i] = h;
        pl[i] = __float2half_rn(v - __half2float(h));
    }
}

// ---------------- launch ----------------
extern "C" void kernel_launch(void* const* d_in, const int* in_sizes, int n_in,
                              void* d_out, int out_size)
{
    const float* x  = (const float*)d_in[0];
    const float* Wq = (const float*)d_in[1];
    const float* bq = (const float*)d_in[2];
    const float* Wk = (const float*)d_in[3];
    const float* bk = (const float*)d_in[4];
    const float* Wv = (const float*)d_in[5];
    const float* bv = (const float*)d_in[6];
    float* out = (float*)d_out;

    __half *Xhi, *Xlo, *Whi, *Wlo, *Qhi, *Qlo, *Ks, *Vs, *Vt, *Phi, *Plo;
    float* P;
    cudaGetSymbolAddress((void**)&Xhi, g_Xhi);
    cudaGetSymbolAddress((void**)&Xlo, g_Xlo);
    cudaGetSymbolAddress((void**)&Whi, g_Whi);
    cudaGetSymbolAddress((void**)&Wlo, g_Wlo);
    cudaGetSymbolAddress((void**)&Qhi, g_Qhi);
    cudaGetSymbolAddress((void**)&Qlo, g_Qlo);
    cudaGetSymbolAddress((void**)&Ks, g_Ks);
    cudaGetSymbolAddress((void**)&Vs, g_Vs);
    cudaGetSymbolAddress((void**)&Vt, g_Vt);
    cudaGetSymbolAddress((void**)&P, g_P);
    cudaGetSymbolAddress((void**)&Phi, g_Phi);
    cudaGetSymbolAddress((void**)&Plo, g_Plo);

    cudaFuncSetAttribute(tgemm<3, 2, true, 1>, cudaFuncAttributeMaxDynamicSharedMemorySize, SM3);
    cudaFuncSetAttribute(tgemm<3, 2, true, 2>, cudaFuncAttributeMaxDynamicSharedMemorySize, SM3);
    cudaFuncSetAttribute(tgemm<2, 3, false, 0>, cudaFuncAttributeMaxDynamicSharedMemorySize, SM2);

    // 1. operand conversion (fp16 hi/lo)
    convert_x<<<16384, 256>>>((const float4*)x, (uint2*)Xhi, (uint2*)Xlo);
    convert_wt<<<dim3(32, 32, 3), 256>>>(Wq, Wk, Wv, Whi, Wlo);

    // 2. projections (3-pass, both sides split): Q -> fp16 pair; K, V -> fp16 single
    tgemm<3, 2, true, 1><<<dim3(8, 128, 1), 256, SM3>>>(
        Xhi, Xlo, 1024, 0, Whi + 0L, Wlo + 0L, 1024, 0,
        bq, 1.f, 1024, nullptr, Qhi, Qlo, 1024, 0);
    tgemm<3, 2, true, 2><<<dim3(8, 128, 1), 256, SM3>>>(
        Xhi, Xlo, 1024, 0, Whi + 1048576L, Wlo + 1048576L, 1024, 0,
        bk, 1.f, 1024, nullptr, Ks, nullptr, 1024, 0);
    tgemm<3, 2, true, 2><<<dim3(8, 128, 1), 256, SM3>>>(
        Xhi, Xlo, 1024, 0, Whi + 2097152L, Wlo + 2097152L, 1024, 0,
        bv, 1.f, 1024, nullptr, Vs, nullptr, 1024, 0);

    // 3. transpose V -> Vt [b, n, s]
    transpose_h<<<dim3(128, 32, 4), 256>>>(Vs, Vt);

    // 4. scores (2-pass: Q pair x K single): P = (1/32) Q K^T, fp32
    tgemm<2, 3, false, 0><<<dim3(32, 32, 4), 256, SM2>>>(
        Qhi, Qlo, 1024, 4194304L, Ks, nullptr, 1024, 4194304L,
        nullptr, 0.03125f, 1024, P, nullptr, nullptr, 4096, 16777216L);

    // 5. softmax rows -> fp16 pair
    softmax_k<<<16384, 256>>>(P, Phi, Plo);

    // 6. out = P V (2-pass: P pair x Vt single)
    tgemm<2, 3, false, 0><<<dim3(8, 32, 4), 256, SM2>>>(
        Phi, Plo, 4096, 16777216L, Vt, nullptr, 4096, 4194304L,
        nullptr, 1.f, 4096, out, nullptr, nullptr, 1024, 4194304L);
}